// round 8
// baseline (speedup 1.0000x reference)
#include <cuda_runtime.h>
#include <cstdint>

// MeanAggregator: out[b, :] = (1/S) * sum_{s<S} features[neigh_idx[b,s], :]
// B=50000, S=10, N=1e6, D=128 (fp32), neigh_idx int32.
// R8: cp.async gather split into TWO commit groups (5+5). Accumulate group A
// under wait_group 1 while group B's loads are still in flight — hides half
// the accumulate latency and shortens each warp's critical path (warp stalls
// on max-of-5 instead of max-of-10 random DRAM latencies before starting
// useful work). 4 warps/block so smem (20.5KB) doesn't cap occupancy.

#define D_DIM 128
#define WARPS_PER_BLOCK 4
#define BLOCK_THREADS (WARPS_PER_BLOCK * 32)

__device__ __forceinline__ unsigned smem_u32(const void* p) {
    return (unsigned)__cvta_generic_to_shared(p);
}

__device__ __forceinline__ void cp_async16(unsigned dst, const void* src) {
    asm volatile("cp.async.cg.shared.global [%0], [%1], 16;"
                 :: "r"(dst), "l"(src) : "memory");
}

template<int S>
__global__ __launch_bounds__(BLOCK_THREADS)
void mean_agg_cpasync(const int* __restrict__ neigh_idx,
                      const float* __restrict__ features,
                      float* __restrict__ out,
                      int B, float inv_s)
{
    static_assert(S == 10, "tuned for S=10");
    constexpr int SA = 5, SB = 5;

    __shared__ __align__(16) float stage[WARPS_PER_BLOCK][S][D_DIM];

    int wib  = threadIdx.x >> 5;
    int warp = blockIdx.x * WARPS_PER_BLOCK + wib;
    int lane = threadIdx.x & 31;
    if (warp >= B) return;

    const int* __restrict__ idx_row = neigh_idx + (long long)warp * S;

    int rows[S];
#pragma unroll
    for (int s = 0; s < S; s++) rows[s] = __ldg(idx_row + s);

    // Group A: rows 0..4
#pragma unroll
    for (int s = 0; s < SA; s++) {
        const float* src = features + (long long)rows[s] * D_DIM + lane * 4;
        cp_async16(smem_u32(&stage[wib][s][lane * 4]), src);
    }
    asm volatile("cp.async.commit_group;" ::: "memory");

    // Group B: rows 5..9
#pragma unroll
    for (int s = SA; s < S; s++) {
        const float* src = features + (long long)rows[s] * D_DIM + lane * 4;
        cp_async16(smem_u32(&stage[wib][s][lane * 4]), src);
    }
    asm volatile("cp.async.commit_group;" ::: "memory");

    // Wait for group A only; accumulate it while group B is in flight.
    asm volatile("cp.async.wait_group 1;" ::: "memory");
    float4 acc = make_float4(0.f, 0.f, 0.f, 0.f);
#pragma unroll
    for (int s = 0; s < SA; s++) {
        float4 v = *reinterpret_cast<const float4*>(&stage[wib][s][lane * 4]);
        acc.x += v.x; acc.y += v.y; acc.z += v.z; acc.w += v.w;
    }

    // Now group B.
    asm volatile("cp.async.wait_group 0;" ::: "memory");
#pragma unroll
    for (int s = SA; s < S; s++) {
        float4 v = *reinterpret_cast<const float4*>(&stage[wib][s][lane * 4]);
        acc.x += v.x; acc.y += v.y; acc.z += v.z; acc.w += v.w;
    }

    acc.x *= inv_s; acc.y *= inv_s; acc.z *= inv_s; acc.w *= inv_s;
    reinterpret_cast<float4*>(out + (long long)warp * D_DIM)[lane] = acc;
}

// Generic fallback (S not known at compile time).
__global__ __launch_bounds__(256)
void mean_agg_kernel_dyn(const int* __restrict__ neigh_idx,
                         const float* __restrict__ features,
                         float* __restrict__ out,
                         int B, int S, float inv_s)
{
    int warp = (blockIdx.x * blockDim.x + threadIdx.x) >> 5;
    int lane = threadIdx.x & 31;
    if (warp >= B) return;

    const int* __restrict__ idx_row = neigh_idx + (long long)warp * S;
    float4 acc = make_float4(0.f, 0.f, 0.f, 0.f);
    for (int s = 0; s < S; s++) {
        int r = idx_row[s];
        float4 vv = __ldg(reinterpret_cast<const float4*>(
            features + (long long)r * D_DIM) + lane);
        acc.x += vv.x; acc.y += vv.y; acc.z += vv.z; acc.w += vv.w;
    }
    acc.x *= inv_s; acc.y *= inv_s; acc.z *= inv_s; acc.w *= inv_s;
    reinterpret_cast<float4*>(out + (long long)warp * D_DIM)[lane] = acc;
}

extern "C" void kernel_launch(void* const* d_in, const int* in_sizes, int n_in,
                              void* d_out, int out_size)
{
    const int*   neigh_idx = (const int*)d_in[0];   // [B, S] int32
    const float* features  = (const float*)d_in[1]; // [N, D] fp32

    int B = out_size / D_DIM;
    int S = in_sizes[0] / B;
    float inv_s = 1.0f / (float)S;
    float* out = (float*)d_out;

    if (S == 10) {
        int grid = (B + WARPS_PER_BLOCK - 1) / WARPS_PER_BLOCK;
        mean_agg_cpasync<10><<<grid, BLOCK_THREADS>>>(neigh_idx, features, out, B, inv_s);
    } else {
        int warps_per_block = 256 / 32;
        int grid = (B + warps_per_block - 1) / warps_per_block;
        mean_agg_kernel_dyn<<<grid, 256>>>(neigh_idx, features, out, B, S, inv_s);
    }
}

// round 9
// speedup vs baseline: 1.0062x; 1.0062x over previous
#include <cuda_runtime.h>
#include <cstdint>

// MeanAggregator: out[b, :] = (1/S) * sum_{s<S} features[neigh_idx[b,s], :]
// B=50000, S=10, N=1e6, D=128 (fp32), neigh_idx int32.
//
// FINAL (R9 = best-measured R7 structure, cleaned):
//   - warp per node; each lane cp.asyncs 16B of each 512B feature row into
//     smem (LDGSTS has no destination register, so all 10 row-copies issue
//     back-to-back: guaranteed MLP=10/warp, immune to ptxas's regs=32
//     load-chain serialization that capped the register-gather variants).
//   - single commit group (measured better than 5+5 split in R8).
//   - no __syncwarp: each lane reads back exactly the bytes it copied, so
//     cp.async.wait_group 0 alone provides the ordering.
//
// Measured ceiling analysis: all structures converge at 5.8-5.9 TB/s
// (73-74% of spec) moving ~240 MB (floor 229 MB) — the DRAM-efficiency
// limit for random 512B-granule reads. Cache-policy hints, chain splitting,
// and pipelined groups all measured neutral or worse.

#define D_DIM 128
#define WARPS_PER_BLOCK 8
#define BLOCK_THREADS (WARPS_PER_BLOCK * 32)

__device__ __forceinline__ unsigned smem_u32(const void* p) {
    return (unsigned)__cvta_generic_to_shared(p);
}

__device__ __forceinline__ void cp_async16(unsigned dst, const void* src) {
    asm volatile("cp.async.cg.shared.global [%0], [%1], 16;"
                 :: "r"(dst), "l"(src) : "memory");
}

template<int S>
__global__ __launch_bounds__(BLOCK_THREADS)
void mean_agg_cpasync(const int* __restrict__ neigh_idx,
                      const float* __restrict__ features,
                      float* __restrict__ out,
                      int B, float inv_s)
{
    __shared__ __align__(16) float stage[WARPS_PER_BLOCK][S][D_DIM];

    int wib  = threadIdx.x >> 5;                   // warp in block
    int warp = blockIdx.x * WARPS_PER_BLOCK + wib; // node id
    int lane = threadIdx.x & 31;
    if (warp >= B) return;

    const int* __restrict__ idx_row = neigh_idx + (long long)warp * S;

    int rows[S];
#pragma unroll
    for (int s = 0; s < S; s++) rows[s] = __ldg(idx_row + s);

    // Issue all S async row-copies back-to-back: 16B per lane per row,
    // 512B per row across the warp (4 x 128B lines, fully coalesced).
#pragma unroll
    for (int s = 0; s < S; s++) {
        const float* src = features + (long long)rows[s] * D_DIM + lane * 4;
        cp_async16(smem_u32(&stage[wib][s][lane * 4]), src);
    }
    asm volatile("cp.async.commit_group;" ::: "memory");
    asm volatile("cp.async.wait_group 0;" ::: "memory");

    // Each lane reads back exactly the 16B it copied — no cross-lane
    // dependency, so no __syncwarp needed.
    float4 acc = make_float4(0.f, 0.f, 0.f, 0.f);
#pragma unroll
    for (int s = 0; s < S; s++) {
        float4 v = *reinterpret_cast<const float4*>(&stage[wib][s][lane * 4]);
        acc.x += v.x; acc.y += v.y; acc.z += v.z; acc.w += v.w;
    }
    acc.x *= inv_s; acc.y *= inv_s; acc.z *= inv_s; acc.w *= inv_s;

    reinterpret_cast<float4*>(out + (long long)warp * D_DIM)[lane] = acc;
}

// Generic fallback (S not known at compile time).
__global__ __launch_bounds__(256)
void mean_agg_kernel_dyn(const int* __restrict__ neigh_idx,
                         const float* __restrict__ features,
                         float* __restrict__ out,
                         int B, int S, float inv_s)
{
    int warp = (blockIdx.x * blockDim.x + threadIdx.x) >> 5;
    int lane = threadIdx.x & 31;
    if (warp >= B) return;

    const int* __restrict__ idx_row = neigh_idx + (long long)warp * S;
    float4 acc = make_float4(0.f, 0.f, 0.f, 0.f);
    for (int s = 0; s < S; s++) {
        int r = idx_row[s];
        float4 vv = __ldg(reinterpret_cast<const float4*>(
            features + (long long)r * D_DIM) + lane);
        acc.x += vv.x; acc.y += vv.y; acc.z += vv.z; acc.w += vv.w;
    }
    acc.x *= inv_s; acc.y *= inv_s; acc.z *= inv_s; acc.w *= inv_s;
    reinterpret_cast<float4*>(out + (long long)warp * D_DIM)[lane] = acc;
}

extern "C" void kernel_launch(void* const* d_in, const int* in_sizes, int n_in,
                              void* d_out, int out_size)
{
    const int*   neigh_idx = (const int*)d_in[0];   // [B, S] int32
    const float* features  = (const float*)d_in[1]; // [N, D] fp32

    int B = out_size / D_DIM;
    int S = in_sizes[0] / B;
    float inv_s = 1.0f / (float)S;
    float* out = (float*)d_out;

    if (S == 10) {
        int grid = (B + WARPS_PER_BLOCK - 1) / WARPS_PER_BLOCK;
        mean_agg_cpasync<10><<<grid, BLOCK_THREADS>>>(neigh_idx, features, out, B, inv_s);
    } else {
        int warps_per_block = 256 / 32;
        int grid = (B + warps_per_block - 1) / warps_per_block;
        mean_agg_kernel_dyn<<<grid, 256>>>(neigh_idx, features, out, B, S, inv_s);
    }
}